// round 7
// baseline (speedup 1.0000x reference)
#include <cuda_runtime.h>

// ---------------------------------------------------------------------------
// SE3 loss, single fused kernel, f32x2-packed (2 elements per thread).
//   rot_loss = mean( (polar_norm(pred_R)^T @ polar_norm(quat_to_R(gt_q)) - I)^2 )
//   t_loss   = mean( (pred_t - gt_t)^2 )
// polar_norm = sign(det) * polar factor via scaled Newton (3 scaled + 1 plain).
// All 3x3 math runs on fma.rn.f32x2 (one instr = 2 fp32 FMAs, sm_103a-only
// pattern ptxas never emits from C++). Lo half = element i, hi half = i+TPB.
// Grid reduction: per-block atomicAdd(double) + last-block finalize/reset.
// ---------------------------------------------------------------------------

#define TPB 256
#define EPB (TPB * 2)

__device__ double g_accum = 0.0;
__device__ unsigned int g_count = 0u;

typedef unsigned long long u64;

// scalar MUFU approx
__device__ __forceinline__ float frcp(float x){ float r; asm("rcp.approx.f32 %0, %1;"   : "=f"(r) : "f"(x)); return r; }
__device__ __forceinline__ float frsq(float x){ float r; asm("rsqrt.approx.f32 %0, %1;" : "=f"(r) : "f"(x)); return r; }
__device__ __forceinline__ float fsqr(float x){ float r; asm("sqrt.approx.f32 %0, %1;"  : "=f"(r) : "f"(x)); return r; }

// packed f32x2 helpers
__device__ __forceinline__ u64 pk(float lo, float hi) {
    u64 r; asm("mov.b64 %0, {%1, %2};" : "=l"(r) : "r"(__float_as_uint(lo)), "r"(__float_as_uint(hi)));
    return r;
}
__device__ __forceinline__ void upk(u64 v, float& lo, float& hi) {
    unsigned int a, b; asm("mov.b64 {%0, %1}, %2;" : "=r"(a), "=r"(b) : "l"(v));
    lo = __uint_as_float(a); hi = __uint_as_float(b);
}
__device__ __forceinline__ u64 f2fma(u64 a, u64 b, u64 c){ u64 d; asm("fma.rn.f32x2 %0, %1, %2, %3;" : "=l"(d) : "l"(a), "l"(b), "l"(c)); return d; }
__device__ __forceinline__ u64 f2mul(u64 a, u64 b){ u64 d; asm("mul.rn.f32x2 %0, %1, %2;" : "=l"(d) : "l"(a), "l"(b)); return d; }
__device__ __forceinline__ u64 f2add(u64 a, u64 b){ u64 d; asm("add.rn.f32x2 %0, %1, %2;" : "=l"(d) : "l"(a), "l"(b)); return d; }
__device__ __forceinline__ u64 f2neg(u64 a){ return a ^ 0x8000000080000000ULL; }
__device__ __forceinline__ u64 f2rcp(u64 a){ float lo, hi; upk(a, lo, hi); return pk(frcp(lo), frcp(hi)); }
__device__ __forceinline__ u64 f2sqrt(u64 a){ float lo, hi; upk(a, lo, hi); return pk(fsqr(lo), fsqr(hi)); }
__device__ __forceinline__ u64 f2rsqrt(u64 a){ float lo, hi; upk(a, lo, hi); return pk(frsq(lo), frsq(hi)); }

#define C_HALF 0x3F0000003F000000ULL   // (0.5, 0.5)
#define C_ONE  0x3F8000003F800000ULL   // (1.0, 1.0)
#define C_TWO  0x4000000040000000ULL   // (2.0, 2.0)
#define C_NONE 0xBF800000BF800000ULL   // (-1.0, -1.0)
#define C_SGN  0x8000000080000000ULL   // sign bits

// In-place packed polar factor of two row-major 3x3 matrices (lo/hi halves).
// Returns packed sign(det) of the original matrices.
// Iters 0..2: Frobenius-scaled Newton X <- 0.5*(mu*X + (1/mu)*X^{-T})
// Iter  3   : plain Newton            X <- 0.5*(X + X^{-T})
__device__ __forceinline__ u64 polar3x3p(u64 X[9]) {
    u64 sgn = C_ONE;
    #pragma unroll
    for (int it = 0; it < 4; ++it) {
        // cofactor matrix (row-major => X^{-T} = C * (1/det))
        u64 c0 = f2fma(X[4], X[8], f2neg(f2mul(X[5], X[7])));
        u64 c1 = f2fma(X[5], X[6], f2neg(f2mul(X[3], X[8])));
        u64 c2 = f2fma(X[3], X[7], f2neg(f2mul(X[4], X[6])));
        u64 c3 = f2fma(X[2], X[7], f2neg(f2mul(X[1], X[8])));
        u64 c4 = f2fma(X[0], X[8], f2neg(f2mul(X[2], X[6])));
        u64 c5 = f2fma(X[1], X[6], f2neg(f2mul(X[0], X[7])));
        u64 c6 = f2fma(X[1], X[5], f2neg(f2mul(X[2], X[4])));
        u64 c7 = f2fma(X[2], X[3], f2neg(f2mul(X[0], X[5])));
        u64 c8 = f2fma(X[0], X[4], f2neg(f2mul(X[1], X[3])));
        u64 det = f2fma(X[0], c0, f2fma(X[1], c1, f2mul(X[2], c2)));
        if (it == 0) sgn = (det & C_SGN) | C_ONE;   // packed copysign(1, det)
        u64 rdet = f2rcp(det);

        u64 a, b;
        if (it < 3) {
            u64 nxa = f2fma(X[0], X[0], f2fma(X[1], X[1], f2mul(X[2], X[2])));
            u64 nxb = f2fma(X[3], X[3], f2fma(X[4], X[4], f2mul(X[5], X[5])));
            u64 nxc = f2fma(X[6], X[6], f2fma(X[7], X[7], f2mul(X[8], X[8])));
            u64 nx  = f2add(f2add(nxa, nxb), nxc);
            u64 nca = f2fma(c0, c0, f2fma(c1, c1, f2mul(c2, c2)));
            u64 ncb = f2fma(c3, c3, f2fma(c4, c4, f2mul(c5, c5)));
            u64 ncc = f2fma(c6, c6, f2fma(c7, c7, f2mul(c8, c8)));
            u64 nc  = f2add(f2add(nca, ncb), ncc);
            // r = |X^{-1}|^2/|X|^2 = nc*rdet^2/nx ;  mu = r^{1/4}
            u64 r   = f2mul(f2mul(nc, f2mul(rdet, rdet)), f2rcp(nx));
            u64 mu2 = f2sqrt(r);                       // mu^2
            a = f2mul((u64)C_HALF, f2sqrt(mu2));       // 0.5*mu
            b = f2mul(f2mul((u64)C_HALF, rdet), f2rsqrt(mu2)); // 0.5/(mu*det)
        } else {
            a = C_HALF;
            b = f2mul((u64)C_HALF, rdet);
        }

        X[0] = f2fma(a, X[0], f2mul(b, c0));
        X[1] = f2fma(a, X[1], f2mul(b, c1));
        X[2] = f2fma(a, X[2], f2mul(b, c2));
        X[3] = f2fma(a, X[3], f2mul(b, c3));
        X[4] = f2fma(a, X[4], f2mul(b, c4));
        X[5] = f2fma(a, X[5], f2mul(b, c5));
        X[6] = f2fma(a, X[6], f2mul(b, c6));
        X[7] = f2fma(a, X[7], f2mul(b, c7));
        X[8] = f2fma(a, X[8], f2mul(b, c8));
    }
    return sgn;
}

__global__ void __launch_bounds__(TPB)
se3_loss_kernel(const float* __restrict__ pred_R,
                const float* __restrict__ pred_t,
                const float* __restrict__ gt,
                float* __restrict__ out,
                int B, int nblocks) {
    __shared__ float sR[EPB * 9];   // 18432 B
    __shared__ float sQ[EPB * 7];   // 14336 B
    __shared__ float sT[EPB * 3];   //  6144 B

    const int tid = threadIdx.x;
    const size_t base = (size_t)blockIdx.x * EPB;
    const bool full = (base + EPB <= (size_t)B);

    // ---- coalesced float4 staging into shared ----
    if (full) {
        const float4* r4 = (const float4*)(pred_R + base * 9);
        float4* s4 = (float4*)sR;
        for (int j = tid; j < (EPB * 9) / 4; j += TPB) s4[j] = r4[j];
        const float4* q4 = (const float4*)(gt + base * 7);
        float4* sq4 = (float4*)sQ;
        for (int j = tid; j < (EPB * 7) / 4; j += TPB) sq4[j] = q4[j];
        const float4* t4 = (const float4*)(pred_t + base * 3);
        float4* st4 = (float4*)sT;
        for (int j = tid; j < (EPB * 3) / 4; j += TPB) st4[j] = t4[j];
    } else {
        int n = (int)((size_t)B > base ? (size_t)B - base : 0);
        for (int j = tid; j < n * 9; j += TPB) sR[j] = pred_R[base * 9 + j];
        for (int j = tid; j < n * 7; j += TPB) sQ[j] = gt[base * 7 + j];
        for (int j = tid; j < n * 3; j += TPB) sT[j] = pred_t[base * 3 + j];
    }
    __syncthreads();

    // lo half = element tid, hi half = element tid+TPB
    const int i0 = tid, i1 = tid + TPB;

    // ---- pred rotation packed (stride 9 -> conflict-free LDS) ----
    u64 P[9];
    #pragma unroll
    for (int i = 0; i < 9; ++i) P[i] = pk(sR[i0 * 9 + i], sR[i1 * 9 + i]);
    u64 sp = polar3x3p(P);

    // ---- gt quat -> matrix packed ----
    u64 qw = pk(sQ[i0*7+0], sQ[i1*7+0]);
    u64 qx = pk(sQ[i0*7+1], sQ[i1*7+1]);
    u64 qy = pk(sQ[i0*7+2], sQ[i1*7+2]);
    u64 qz = pk(sQ[i0*7+3], sQ[i1*7+3]);
    u64 G[9];
    {
        u64 two = C_TWO, one = C_ONE;
        u64 yy_zz = f2fma(qy, qy, f2mul(qz, qz));
        u64 xx_zz = f2fma(qx, qx, f2mul(qz, qz));
        u64 xx_yy = f2fma(qx, qx, f2mul(qy, qy));
        G[0] = f2fma(f2neg(two), yy_zz, one);
        G[4] = f2fma(f2neg(two), xx_zz, one);
        G[8] = f2fma(f2neg(two), xx_yy, one);
        u64 xy = f2mul(qx, qy), wz = f2mul(qw, qz);
        u64 xz = f2mul(qx, qz), wy = f2mul(qw, qy);
        u64 yz = f2mul(qy, qz), wx = f2mul(qw, qx);
        G[1] = f2mul(two, f2add(xy, f2neg(wz)));
        G[3] = f2mul(two, f2add(xy, wz));
        G[2] = f2mul(two, f2add(xz, wy));
        G[6] = f2mul(two, f2add(xz, f2neg(wy)));
        G[5] = f2mul(two, f2add(yz, f2neg(wx)));
        G[7] = f2mul(two, f2add(yz, wx));
    }
    u64 sg = polar3x3p(G);
    u64 sig = f2mul(sp, sg);

    // ---- M = P^T @ G ; rot contribution ----
    u64 rot = 0ULL;  // (+0.0f, +0.0f)
    #pragma unroll
    for (int i = 0; i < 3; ++i) {
        #pragma unroll
        for (int k = 0; k < 3; ++k) {
            u64 m = f2fma(P[i], G[k], f2fma(P[3+i], G[3+k], f2mul(P[6+i], G[6+k])));
            u64 m2 = (i == k) ? f2fma(sig, m, (u64)C_NONE) : f2mul(sig, m);
            rot = f2fma(m2, m2, rot);
        }
    }

    // ---- translation ----
    u64 t0 = f2add(pk(sT[i0*3+0], sT[i1*3+0]), f2neg(pk(sQ[i0*7+4], sQ[i1*7+4])));
    u64 t1 = f2add(pk(sT[i0*3+1], sT[i1*3+1]), f2neg(pk(sQ[i0*7+5], sQ[i1*7+5])));
    u64 t2 = f2add(pk(sT[i0*3+2], sT[i1*3+2]), f2neg(pk(sQ[i0*7+6], sQ[i1*7+6])));
    u64 tl = f2fma(t0, t0, f2fma(t1, t1, f2mul(t2, t2)));

    // v = rot/9 + tl/3  (packed)
    u64 vp = f2fma(rot, pk(1.0f/9.0f, 1.0f/9.0f), f2mul(tl, pk(1.0f/3.0f, 1.0f/3.0f)));
    float vlo, vhi; upk(vp, vlo, vhi);
    float v = 0.0f;
    if (base + (size_t)i0 < (size_t)B) v += vlo;
    if (base + (size_t)i1 < (size_t)B) v += vhi;

    // ---- block reduction ----
    #pragma unroll
    for (int o = 16; o > 0; o >>= 1) v += __shfl_xor_sync(0xFFFFFFFFu, v, o);

    __shared__ float sh[TPB / 32];
    int lane = tid & 31;
    int warp = tid >> 5;
    if (lane == 0) sh[warp] = v;
    __syncthreads();
    if (warp == 0) {
        v = (lane < TPB / 32) ? sh[lane] : 0.0f;
        #pragma unroll
        for (int o = 16; o > 0; o >>= 1) v += __shfl_xor_sync(0xFFFFFFFFu, v, o);
        if (lane == 0) {
            atomicAdd(&g_accum, (double)v);
            __threadfence();
            unsigned int prev = atomicAdd(&g_count, 1u);
            if (prev == (unsigned int)(nblocks - 1)) {
                double total = atomicAdd(&g_accum, 0.0);  // atomic read at L2
                *out = (float)(total / (double)B);
                g_accum = 0.0;                             // reset for next replay
                g_count = 0u;
            }
        }
    }
}

extern "C" void kernel_launch(void* const* d_in, const int* in_sizes, int n_in,
                              void* d_out, int out_size) {
    (void)n_in; (void)out_size;
    const float* pred_R = (const float*)d_in[0];
    const float* pred_t = (const float*)d_in[1];
    const float* gt     = (const float*)d_in[2];
    int B = in_sizes[0] / 9;

    int blocks = (B + EPB - 1) / EPB;
    se3_loss_kernel<<<blocks, TPB>>>(pred_R, pred_t, gt, (float*)d_out, B, blocks);
}

// round 10
// speedup vs baseline: 1.1461x; 1.1461x over previous
#include <cuda_runtime.h>

// ---------------------------------------------------------------------------
// SE3 loss, single fused kernel (scalar fp32, issue-optimized):
//   rot_loss = mean( (polar_norm(pred_R)^T @ polar_norm(quat_to_R(gt_q)) - I)^2 )
//   t_loss   = mean( (pred_t - gt_t)^2 )
// polar_norm(R) = sign(det R) * polar factor, via Newton iteration:
//   iters 0..2 Frobenius-scaled, iter 3 plain. (4 iters verified: the packed
//   R4 kernel used identical math and measured rel_err 0.0.)
// Grid reduction: block shuffle-reduce -> atomicAdd(double) -> last-block
// finalize + reset of device globals (graph-replay safe).
// ---------------------------------------------------------------------------

#define TPB 256

__device__ double g_accum = 0.0;
__device__ unsigned int g_count = 0u;

__device__ __forceinline__ float frcp(float x)  { float r; asm("rcp.approx.f32 %0, %1;"   : "=f"(r) : "f"(x)); return r; }
__device__ __forceinline__ float frsq(float x)  { float r; asm("rsqrt.approx.f32 %0, %1;" : "=f"(r) : "f"(x)); return r; }
__device__ __forceinline__ float fsqr(float x)  { float r; asm("sqrt.approx.f32 %0, %1;"  : "=f"(r) : "f"(x)); return r; }

// In-place polar factor of row-major 3x3. Returns sign(det) of the original.
// Iters 0..2: scaled Newton  X <- 0.5*(mu*X + (1/mu)*X^{-T}),
//             mu = (|X^{-1}|_F^2 / |X|_F^2)^{1/4}
// Iter  3   : plain Newton   X <- 0.5*(X + X^{-T})
__device__ __forceinline__ float polar3x3(float X[9]) {
    float sgn = 1.0f;
    #pragma unroll
    for (int it = 0; it < 4; ++it) {
        // cofactor matrix, row-major (so X^{-T} = C * (1/det))
        float c0 = fmaf(X[4], X[8], -X[5]*X[7]);
        float c1 = fmaf(X[5], X[6], -X[3]*X[8]);
        float c2 = fmaf(X[3], X[7], -X[4]*X[6]);
        float c3 = fmaf(X[2], X[7], -X[1]*X[8]);
        float c4 = fmaf(X[0], X[8], -X[2]*X[6]);
        float c5 = fmaf(X[1], X[6], -X[0]*X[7]);
        float c6 = fmaf(X[1], X[5], -X[2]*X[4]);
        float c7 = fmaf(X[2], X[3], -X[0]*X[5]);
        float c8 = fmaf(X[0], X[4], -X[1]*X[3]);
        float det = fmaf(X[0], c0, fmaf(X[1], c1, X[2]*c2));
        if (it == 0) {
            // branchless copysign(1.0f, det)
            sgn = __int_as_float((__float_as_int(det) & 0x80000000) | 0x3F800000);
        }
        float rdet = frcp(det);

        float a, b;
        if (it < 3) {
            float nx = X[0]*X[0];
            #pragma unroll
            for (int i = 1; i < 9; ++i) nx = fmaf(X[i], X[i], nx);
            float nc = c0*c0;
            nc = fmaf(c1,c1,nc); nc = fmaf(c2,c2,nc); nc = fmaf(c3,c3,nc);
            nc = fmaf(c4,c4,nc); nc = fmaf(c5,c5,nc); nc = fmaf(c6,c6,nc);
            nc = fmaf(c7,c7,nc); nc = fmaf(c8,c8,nc);
            // r = |X^{-1}|^2/|X|^2 ;  mu = r^{1/4}
            float r   = nc * rdet * rdet * frcp(nx);
            float mu2 = fsqr(r);                 // mu^2
            a = 0.5f * fsqr(mu2);                // 0.5*mu
            b = 0.5f * rdet * frsq(mu2);         // 0.5*(1/mu)/det
        } else {
            a = 0.5f;
            b = 0.5f * rdet;
        }

        X[0] = fmaf(a, X[0], b*c0);
        X[1] = fmaf(a, X[1], b*c1);
        X[2] = fmaf(a, X[2], b*c2);
        X[3] = fmaf(a, X[3], b*c3);
        X[4] = fmaf(a, X[4], b*c4);
        X[5] = fmaf(a, X[5], b*c5);
        X[6] = fmaf(a, X[6], b*c6);
        X[7] = fmaf(a, X[7], b*c7);
        X[8] = fmaf(a, X[8], b*c8);
    }
    return sgn;
}

__global__ void __launch_bounds__(TPB)
se3_loss_kernel(const float* __restrict__ pred_R,
                const float* __restrict__ pred_t,
                const float* __restrict__ gt,
                float* __restrict__ out,
                int B, int nblocks) {
    __shared__ float sR[TPB * 9];
    __shared__ float sQ[TPB * 7];
    __shared__ float sT[TPB * 3];

    const int tid = threadIdx.x;
    const size_t base = (size_t)blockIdx.x * TPB;
    const bool full = (base + TPB <= (size_t)B);

    // ---- coalesced float4 staging into shared ----
    if (full) {
        const float4* r4 = (const float4*)(pred_R + base * 9);   // 576 float4
        float4* s4 = (float4*)sR;
        #pragma unroll
        for (int i = 0; i < 3; ++i) {
            int j = tid + i * TPB;
            if (j < (TPB*9)/4) s4[j] = r4[j];
        }
        const float4* q4 = (const float4*)(gt + base * 7);       // 448 float4
        float4* sq4 = (float4*)sQ;
        #pragma unroll
        for (int i = 0; i < 2; ++i) {
            int j = tid + i * TPB;
            if (j < (TPB*7)/4) sq4[j] = q4[j];
        }
        const float4* t4 = (const float4*)(pred_t + base * 3);   // 192 float4
        float4* st4 = (float4*)sT;
        if (tid < (TPB*3)/4) st4[tid] = t4[tid];
    } else {
        int n = (int)((size_t)B > base ? (size_t)B - base : 0);
        for (int j = tid; j < n * 9; j += TPB) sR[j] = pred_R[base * 9 + j];
        for (int j = tid; j < n * 7; j += TPB) sQ[j] = gt[base * 7 + j];
        for (int j = tid; j < n * 3; j += TPB) sT[j] = pred_t[base * 3 + j];
    }
    __syncthreads();

    float v = 0.0f;
    const int idx = (int)base + tid;
    if (idx < B) {
        // ---- pred rotation (stride 9 -> conflict-free LDS) ----
        float P[9];
        #pragma unroll
        for (int i = 0; i < 9; ++i) P[i] = sR[tid * 9 + i];
        float sp = polar3x3(P);

        // ---- gt quat -> matrix -> polar ----
        float qw = sQ[tid*7+0], qx = sQ[tid*7+1], qy = sQ[tid*7+2], qz = sQ[tid*7+3];
        // hoist translation LDS so they overlap polar latency
        float gt0 = sQ[tid*7+4], gt1 = sQ[tid*7+5], gt2 = sQ[tid*7+6];
        float pt0 = sT[tid*3+0], pt1 = sT[tid*3+1], pt2 = sT[tid*3+2];

        float G[9];
        G[0] = 1.0f - 2.0f*(qy*qy + qz*qz);
        G[1] = 2.0f*(qx*qy - qw*qz);
        G[2] = 2.0f*(qx*qz + qw*qy);
        G[3] = 2.0f*(qx*qy + qw*qz);
        G[4] = 1.0f - 2.0f*(qx*qx + qz*qz);
        G[5] = 2.0f*(qy*qz - qw*qx);
        G[6] = 2.0f*(qx*qz - qw*qy);
        G[7] = 2.0f*(qy*qz + qw*qx);
        G[8] = 1.0f - 2.0f*(qx*qx + qy*qy);
        float sg = polar3x3(G);

        float sig = sp * sg;

        // ---- M = P^T @ G ; rot contribution ----
        float rot = 0.0f;
        #pragma unroll
        for (int i = 0; i < 3; ++i) {
            #pragma unroll
            for (int k = 0; k < 3; ++k) {
                float m = fmaf(P[i], G[k], fmaf(P[3+i], G[3+k], P[6+i]*G[6+k]));
                m = sig * m - ((i == k) ? 1.0f : 0.0f);
                rot = fmaf(m, m, rot);
            }
        }

        // ---- translation ----
        float t0 = pt0 - gt0 * 0.0f - gt0;  // keep simple: pt - gt
        t0 = pt0 - gt0;
        float t1 = pt1 - gt1;
        float t2 = pt2 - gt2;
        float tl = fmaf(t0, t0, fmaf(t1, t1, t2*t2));

        v = rot * (1.0f/9.0f) + tl * (1.0f/3.0f);
    }

    // ---- block reduction ----
    #pragma unroll
    for (int o = 16; o > 0; o >>= 1) v += __shfl_xor_sync(0xFFFFFFFFu, v, o);

    __shared__ float sh[TPB / 32];
    int lane = tid & 31;
    int warp = tid >> 5;
    if (lane == 0) sh[warp] = v;
    __syncthreads();
    if (warp == 0) {
        v = (lane < TPB/32) ? sh[lane] : 0.0f;
        #pragma unroll
        for (int o = 16; o > 0; o >>= 1) v += __shfl_xor_sync(0xFFFFFFFFu, v, o);
        if (lane == 0) {
            atomicAdd(&g_accum, (double)v);
            __threadfence();
            unsigned int prev = atomicAdd(&g_count, 1u);
            if (prev == (unsigned int)(nblocks - 1)) {
                double total = atomicAdd(&g_accum, 0.0);   // atomic read at L2
                *out = (float)(total / (double)B);
                g_accum = 0.0;                              // reset for next replay
                g_count = 0u;
            }
        }
    }
}

extern "C" void kernel_launch(void* const* d_in, const int* in_sizes, int n_in,
                              void* d_out, int out_size) {
    (void)n_in; (void)out_size;
    const float* pred_R = (const float*)d_in[0];
    const float* pred_t = (const float*)d_in[1];
    const float* gt     = (const float*)d_in[2];
    int B = in_sizes[0] / 9;

    int blocks = (B + TPB - 1) / TPB;
    se3_loss_kernel<<<blocks, TPB>>>(pred_R, pred_t, gt, (float*)d_out, B, blocks);
}

// round 11
// speedup vs baseline: 1.2208x; 1.0651x over previous
#include <cuda_runtime.h>

// ---------------------------------------------------------------------------
// SE3 loss, single fused kernel (scalar fp32, issue-optimized):
//   rot_loss = mean( (polar_norm(pred_R)^T @ polar_norm(quat_to_R(gt_q)) - I)^2 )
//   t_loss   = mean( (pred_t - gt_t)^2 )
// polar_norm(R) = sign(det R) * polar factor:
//   iters 0..2: Frobenius-scaled Newton  X <- 0.5*(mu*X + (1/mu)*X^{-T})
//               (MUFU-reduced: 3 MUFU/iter via w = rsqrt(p*nx) identity)
//   iter  3   : Newton-Schulz            X <- X*(1.5I - 0.5*X^T X)
//               (no rcp in chain; valid since sigma in (0,sqrt(3)) here)
// pred_t loaded directly (3 LDG.32) - no smem staging; smem 16.4KB -> occ up.
// Grid reduction: block shuffle-reduce -> atomicAdd(double) -> last-block
// finalize + reset of device globals (graph-replay safe).
// ---------------------------------------------------------------------------

#define TPB 256

__device__ double g_accum = 0.0;
__device__ unsigned int g_count = 0u;

__device__ __forceinline__ float frcp(float x)  { float r; asm("rcp.approx.f32 %0, %1;"   : "=f"(r) : "f"(x)); return r; }
__device__ __forceinline__ float frsq(float x)  { float r; asm("rsqrt.approx.f32 %0, %1;" : "=f"(r) : "f"(x)); return r; }
__device__ __forceinline__ float fsqr(float x)  { float r; asm("sqrt.approx.f32 %0, %1;"  : "=f"(r) : "f"(x)); return r; }

// In-place polar factor of row-major 3x3. Returns sign(det) of the original.
__device__ __forceinline__ float polar3x3(float X[9]) {
    float sgn = 1.0f;
    #pragma unroll
    for (int it = 0; it < 3; ++it) {
        // cofactor matrix, row-major (so X^{-T} = C * (1/det))
        float c0 = fmaf(X[4], X[8], -X[5]*X[7]);
        float c1 = fmaf(X[5], X[6], -X[3]*X[8]);
        float c2 = fmaf(X[3], X[7], -X[4]*X[6]);
        float c3 = fmaf(X[2], X[7], -X[1]*X[8]);
        float c4 = fmaf(X[0], X[8], -X[2]*X[6]);
        float c5 = fmaf(X[1], X[6], -X[0]*X[7]);
        float c6 = fmaf(X[1], X[5], -X[2]*X[4]);
        float c7 = fmaf(X[2], X[3], -X[0]*X[5]);
        float c8 = fmaf(X[0], X[4], -X[1]*X[3]);
        float det = fmaf(X[0], c0, fmaf(X[1], c1, X[2]*c2));
        if (it == 0) {
            // branchless copysign(1.0f, det)
            sgn = __int_as_float((__float_as_int(det) & 0x80000000) | 0x3F800000);
        }
        float rdet = frcp(det);

        float nx = X[0]*X[0];
        #pragma unroll
        for (int i = 1; i < 9; ++i) nx = fmaf(X[i], X[i], nx);
        float nc = c0*c0;
        nc = fmaf(c1,c1,nc); nc = fmaf(c2,c2,nc); nc = fmaf(c3,c3,nc);
        nc = fmaf(c4,c4,nc); nc = fmaf(c5,c5,nc); nc = fmaf(c6,c6,nc);
        nc = fmaf(c7,c7,nc); nc = fmaf(c8,c8,nc);

        // mu = (nc/(nx*det^2))^{1/4}; with p = nc*rdet^2, w = rsqrt(p*nx):
        //   p*w  = sqrt(p/nx)  = mu^2
        //   nx*w = sqrt(nx/p)  = 1/mu^2
        //   a = 0.5*mu = 0.5*sqrt(p*w)
        //   b = 0.5*rdet/mu = rdet*(nx*w)*a
        float p = nc * rdet * rdet;
        float w = frsq(p * nx);
        float a = 0.5f * fsqr(p * w);
        float b = rdet * (nx * w) * a;

        X[0] = fmaf(a, X[0], b*c0);
        X[1] = fmaf(a, X[1], b*c1);
        X[2] = fmaf(a, X[2], b*c2);
        X[3] = fmaf(a, X[3], b*c3);
        X[4] = fmaf(a, X[4], b*c4);
        X[5] = fmaf(a, X[5], b*c5);
        X[6] = fmaf(a, X[6], b*c6);
        X[7] = fmaf(a, X[7], b*c7);
        X[8] = fmaf(a, X[8], b*c8);
    }

    // Final Newton-Schulz step: X <- X * (1.5I - 0.5 * X^T X)
    {
        float s00 = fmaf(X[0], X[0], fmaf(X[3], X[3], X[6]*X[6]));
        float s11 = fmaf(X[1], X[1], fmaf(X[4], X[4], X[7]*X[7]));
        float s22 = fmaf(X[2], X[2], fmaf(X[5], X[5], X[8]*X[8]));
        float s01 = fmaf(X[0], X[1], fmaf(X[3], X[4], X[6]*X[7]));
        float s02 = fmaf(X[0], X[2], fmaf(X[3], X[5], X[6]*X[8]));
        float s12 = fmaf(X[1], X[2], fmaf(X[4], X[5], X[7]*X[8]));
        float d0 = fmaf(-0.5f, s00, 1.5f);
        float d1 = fmaf(-0.5f, s11, 1.5f);
        float d2 = fmaf(-0.5f, s22, 1.5f);
        float o01 = -0.5f * s01;
        float o02 = -0.5f * s02;
        float o12 = -0.5f * s12;
        #pragma unroll
        for (int r = 0; r < 3; ++r) {
            float x0 = X[3*r+0], x1 = X[3*r+1], x2 = X[3*r+2];
            X[3*r+0] = fmaf(x0, d0,  fmaf(x1, o01, x2*o02));
            X[3*r+1] = fmaf(x0, o01, fmaf(x1, d1,  x2*o12));
            X[3*r+2] = fmaf(x0, o02, fmaf(x1, o12, x2*d2 ));
        }
    }
    return sgn;
}

__global__ void __launch_bounds__(TPB)
se3_loss_kernel(const float* __restrict__ pred_R,
                const float* __restrict__ pred_t,
                const float* __restrict__ gt,
                float* __restrict__ out,
                int B, int nblocks) {
    __shared__ float sR[TPB * 9];   // 9216 B
    __shared__ float sQ[TPB * 7];   // 7168 B

    const int tid = threadIdx.x;
    const size_t base = (size_t)blockIdx.x * TPB;
    const bool full = (base + TPB <= (size_t)B);

    // ---- coalesced float4 staging into shared (R and gt only) ----
    if (full) {
        const float4* r4 = (const float4*)(pred_R + base * 9);   // 576 float4
        float4* s4 = (float4*)sR;
        #pragma unroll
        for (int i = 0; i < 3; ++i) {
            int j = tid + i * TPB;
            if (j < (TPB*9)/4) s4[j] = r4[j];
        }
        const float4* q4 = (const float4*)(gt + base * 7);       // 448 float4
        float4* sq4 = (float4*)sQ;
        #pragma unroll
        for (int i = 0; i < 2; ++i) {
            int j = tid + i * TPB;
            if (j < (TPB*7)/4) sq4[j] = q4[j];
        }
    } else {
        int n = (int)((size_t)B > base ? (size_t)B - base : 0);
        for (int j = tid; j < n * 9; j += TPB) sR[j] = pred_R[base * 9 + j];
        for (int j = tid; j < n * 7; j += TPB) sQ[j] = gt[base * 7 + j];
    }
    __syncthreads();

    float v = 0.0f;
    const int idx = (int)base + tid;
    if (idx < B) {
        // pred_t direct (3 lines/warp per LDG, issues early, overlaps compute)
        const float* tp = pred_t + (size_t)idx * 3;
        float pt0 = __ldg(tp + 0), pt1 = __ldg(tp + 1), pt2 = __ldg(tp + 2);

        // ---- pred rotation (stride 9 -> conflict-free LDS) ----
        float P[9];
        #pragma unroll
        for (int i = 0; i < 9; ++i) P[i] = sR[tid * 9 + i];
        float sp = polar3x3(P);

        // ---- gt quat -> matrix -> polar ----
        float qw = sQ[tid*7+0], qx = sQ[tid*7+1], qy = sQ[tid*7+2], qz = sQ[tid*7+3];
        float gt0 = sQ[tid*7+4], gt1 = sQ[tid*7+5], gt2 = sQ[tid*7+6];

        float G[9];
        G[0] = 1.0f - 2.0f*(qy*qy + qz*qz);
        G[1] = 2.0f*(qx*qy - qw*qz);
        G[2] = 2.0f*(qx*qz + qw*qy);
        G[3] = 2.0f*(qx*qy + qw*qz);
        G[4] = 1.0f - 2.0f*(qx*qx + qz*qz);
        G[5] = 2.0f*(qy*qz - qw*qx);
        G[6] = 2.0f*(qx*qz - qw*qy);
        G[7] = 2.0f*(qy*qz + qw*qx);
        G[8] = 1.0f - 2.0f*(qx*qx + qy*qy);
        float sg = polar3x3(G);

        float sig = sp * sg;

        // ---- M = P^T @ G ; rot contribution ----
        float rot = 0.0f;
        #pragma unroll
        for (int i = 0; i < 3; ++i) {
            #pragma unroll
            for (int k = 0; k < 3; ++k) {
                float m = fmaf(P[i], G[k], fmaf(P[3+i], G[3+k], P[6+i]*G[6+k]));
                m = sig * m - ((i == k) ? 1.0f : 0.0f);
                rot = fmaf(m, m, rot);
            }
        }

        // ---- translation ----
        float t0 = pt0 - gt0;
        float t1 = pt1 - gt1;
        float t2 = pt2 - gt2;
        float tl = fmaf(t0, t0, fmaf(t1, t1, t2*t2));

        v = rot * (1.0f/9.0f) + tl * (1.0f/3.0f);
    }

    // ---- block reduction ----
    #pragma unroll
    for (int o = 16; o > 0; o >>= 1) v += __shfl_xor_sync(0xFFFFFFFFu, v, o);

    __shared__ float sh[TPB / 32];
    int lane = tid & 31;
    int warp = tid >> 5;
    if (lane == 0) sh[warp] = v;
    __syncthreads();
    if (warp == 0) {
        v = (lane < TPB/32) ? sh[lane] : 0.0f;
        #pragma unroll
        for (int o = 16; o > 0; o >>= 1) v += __shfl_xor_sync(0xFFFFFFFFu, v, o);
        if (lane == 0) {
            atomicAdd(&g_accum, (double)v);
            __threadfence();
            unsigned int prev = atomicAdd(&g_count, 1u);
            if (prev == (unsigned int)(nblocks - 1)) {
                double total = atomicAdd(&g_accum, 0.0);   // atomic read at L2
                *out = (float)(total / (double)B);
                g_accum = 0.0;                              // reset for next replay
                g_count = 0u;
            }
        }
    }
}

extern "C" void kernel_launch(void* const* d_in, const int* in_sizes, int n_in,
                              void* d_out, int out_size) {
    (void)n_in; (void)out_size;
    const float* pred_R = (const float*)d_in[0];
    const float* pred_t = (const float*)d_in[1];
    const float* gt     = (const float*)d_in[2];
    int B = in_sizes[0] / 9;

    int blocks = (B + TPB - 1) / TPB;
    se3_loss_kernel<<<blocks, TPB>>>(pred_R, pred_t, gt, (float*)d_out, B, blocks);
}

// round 13
// speedup vs baseline: 1.5171x; 1.2427x over previous
#include <cuda_runtime.h>

// ---------------------------------------------------------------------------
// SE3 loss, single fused kernel (scalar fp32):
//   rot_loss = mean( (polar_norm(pred_R)^T @ polar_norm(quat_to_R(gt_q)) - I)^2 )
//   t_loss   = mean( (pred_t - gt_t)^2 )
//
// pred_R path: polar via 3 Frobenius-scaled Newton iters + 1 Newton-Schulz.
// gt path: ANALYTIC. The unnormalized-quat matrix satisfies
//     G = n^2 * Rhat + (1 - n^2) * I     (n^2 = |q|^2, Rhat = rot of q/|q|)
//   so polar(G) = Rot(u, Theta) about the same axis u:
//     cN = w^2-m^2, sN = 2wm, m = |(x,y,z)|, beta = 1-n^2
//     Nc = n^4*(cN+beta), Ns = n^4*sN  (computed via the equivalent
//     Ap/Bp form); cosTh = Nc*rinv, sinTh = Ns*rinv
//   and det(G) > 0 always, so no sign term for G.
// Grid reduction: block shuffle-reduce -> atomicAdd(double) -> last-block
// finalize + reset of device globals (graph-replay safe).
// ---------------------------------------------------------------------------

#define TPB 256

__device__ double g_accum = 0.0;
__device__ unsigned int g_count = 0u;

__device__ __forceinline__ float frcp(float x)  { float r; asm("rcp.approx.f32 %0, %1;"   : "=f"(r) : "f"(x)); return r; }
__device__ __forceinline__ float frsq(float x)  { float r; asm("rsqrt.approx.f32 %0, %1;" : "=f"(r) : "f"(x)); return r; }
__device__ __forceinline__ float fsqr(float x)  { float r; asm("sqrt.approx.f32 %0, %1;"  : "=f"(r) : "f"(x)); return r; }

// In-place polar factor of row-major 3x3. Returns sign(det) of the original.
__device__ __forceinline__ float polar3x3(float X[9]) {
    float sgn = 1.0f;
    #pragma unroll
    for (int it = 0; it < 3; ++it) {
        // cofactor matrix, row-major (so X^{-T} = C * (1/det))
        float c0 = fmaf(X[4], X[8], -X[5]*X[7]);
        float c1 = fmaf(X[5], X[6], -X[3]*X[8]);
        float c2 = fmaf(X[3], X[7], -X[4]*X[6]);
        float c3 = fmaf(X[2], X[7], -X[1]*X[8]);
        float c4 = fmaf(X[0], X[8], -X[2]*X[6]);
        float c5 = fmaf(X[1], X[6], -X[0]*X[7]);
        float c6 = fmaf(X[1], X[5], -X[2]*X[4]);
        float c7 = fmaf(X[2], X[3], -X[0]*X[5]);
        float c8 = fmaf(X[0], X[4], -X[1]*X[3]);
        float det = fmaf(X[0], c0, fmaf(X[1], c1, X[2]*c2));
        if (it == 0) {
            sgn = __int_as_float((__float_as_int(det) & 0x80000000) | 0x3F800000);
        }
        float rdet = frcp(det);

        float nx = X[0]*X[0];
        #pragma unroll
        for (int i = 1; i < 9; ++i) nx = fmaf(X[i], X[i], nx);
        float nc = c0*c0;
        nc = fmaf(c1,c1,nc); nc = fmaf(c2,c2,nc); nc = fmaf(c3,c3,nc);
        nc = fmaf(c4,c4,nc); nc = fmaf(c5,c5,nc); nc = fmaf(c6,c6,nc);
        nc = fmaf(c7,c7,nc); nc = fmaf(c8,c8,nc);

        // mu = (nc/(nx*det^2))^{1/4}; with p = nc*rdet^2, w = rsqrt(p*nx):
        //   a = 0.5*mu = 0.5*sqrt(p*w);  b = 0.5*rdet/mu = rdet*(nx*w)*a
        float p = nc * rdet * rdet;
        float w = frsq(p * nx);
        float a = 0.5f * fsqr(p * w);
        float b = rdet * (nx * w) * a;

        X[0] = fmaf(a, X[0], b*c0);
        X[1] = fmaf(a, X[1], b*c1);
        X[2] = fmaf(a, X[2], b*c2);
        X[3] = fmaf(a, X[3], b*c3);
        X[4] = fmaf(a, X[4], b*c4);
        X[5] = fmaf(a, X[5], b*c5);
        X[6] = fmaf(a, X[6], b*c6);
        X[7] = fmaf(a, X[7], b*c7);
        X[8] = fmaf(a, X[8], b*c8);
    }

    // Final Newton-Schulz step: X <- X * (1.5I - 0.5 * X^T X)
    {
        float s00 = fmaf(X[0], X[0], fmaf(X[3], X[3], X[6]*X[6]));
        float s11 = fmaf(X[1], X[1], fmaf(X[4], X[4], X[7]*X[7]));
        float s22 = fmaf(X[2], X[2], fmaf(X[5], X[5], X[8]*X[8]));
        float s01 = fmaf(X[0], X[1], fmaf(X[3], X[4], X[6]*X[7]));
        float s02 = fmaf(X[0], X[2], fmaf(X[3], X[5], X[6]*X[8]));
        float s12 = fmaf(X[1], X[2], fmaf(X[4], X[5], X[7]*X[8]));
        float d0 = fmaf(-0.5f, s00, 1.5f);
        float d1 = fmaf(-0.5f, s11, 1.5f);
        float d2 = fmaf(-0.5f, s22, 1.5f);
        float o01 = -0.5f * s01;
        float o02 = -0.5f * s02;
        float o12 = -0.5f * s12;
        #pragma unroll
        for (int r = 0; r < 3; ++r) {
            float x0 = X[3*r+0], x1 = X[3*r+1], x2 = X[3*r+2];
            X[3*r+0] = fmaf(x0, d0,  fmaf(x1, o01, x2*o02));
            X[3*r+1] = fmaf(x0, o01, fmaf(x1, d1,  x2*o12));
            X[3*r+2] = fmaf(x0, o02, fmaf(x1, o12, x2*d2 ));
        }
    }
    return sgn;
}

__global__ void __launch_bounds__(TPB)
se3_loss_kernel(const float* __restrict__ pred_R,
                const float* __restrict__ pred_t,
                const float* __restrict__ gt,
                float* __restrict__ out,
                int B, int nblocks) {
    __shared__ float sR[TPB * 9];   // 9216 B
    __shared__ float sQ[TPB * 7];   // 7168 B

    const int tid = threadIdx.x;
    const size_t base = (size_t)blockIdx.x * TPB;
    const bool full = (base + TPB <= (size_t)B);

    // ---- coalesced float4 staging into shared (R and gt only) ----
    if (full) {
        const float4* r4 = (const float4*)(pred_R + base * 9);   // 576 float4
        float4* s4 = (float4*)sR;
        #pragma unroll
        for (int i = 0; i < 3; ++i) {
            int j = tid + i * TPB;
            if (j < (TPB*9)/4) s4[j] = r4[j];
        }
        const float4* q4 = (const float4*)(gt + base * 7);       // 448 float4
        float4* sq4 = (float4*)sQ;
        #pragma unroll
        for (int i = 0; i < 2; ++i) {
            int j = tid + i * TPB;
            if (j < (TPB*7)/4) sq4[j] = q4[j];
        }
    } else {
        int n = (int)((size_t)B > base ? (size_t)B - base : 0);
        for (int j = tid; j < n * 9; j += TPB) sR[j] = pred_R[base * 9 + j];
        for (int j = tid; j < n * 7; j += TPB) sQ[j] = gt[base * 7 + j];
    }
    __syncthreads();

    float v = 0.0f;
    const int idx = (int)base + tid;
    if (idx < B) {
        // pred_t direct (3 lines/warp per LDG, issues early, overlaps compute)
        const float* tp = pred_t + (size_t)idx * 3;
        float pt0 = __ldg(tp + 0), pt1 = __ldg(tp + 1), pt2 = __ldg(tp + 2);

        // ---- pred rotation: iterative polar ----
        float P[9];
        #pragma unroll
        for (int i = 0; i < 9; ++i) P[i] = sR[tid * 9 + i];
        float sp = polar3x3(P);

        // ---- gt: ANALYTIC polar of the quat matrix ----
        float qw = sQ[tid*7+0], qx = sQ[tid*7+1], qy = sQ[tid*7+2], qz = sQ[tid*7+3];
        float gt0 = sQ[tid*7+4], gt1 = sQ[tid*7+5], gt2 = sQ[tid*7+6];

        float xx = qx*qx, yy = qy*qy, zz = qz*qz;
        float m2 = fmaf(qx, qx, fmaf(qy, qy, zz));
        float n2 = fmaf(qw, qw, m2);
        float rm = frsq(fmaxf(m2, 1e-30f));       // 1/m
        float m  = m2 * rm;                        // m = |(x,y,z)|

        float cN = fmaf(qw, qw, -m2);              // n2*cos(theta)
        float sN = 2.0f * qw * m;                  // n2*sin(theta)
        float beta = 1.0f - n2;
        float Ap = fmaf(n2, n2, beta * cN);
        float Bp = beta * sN;

        float Nc = fmaf(cN, Ap,  sN * Bp);         // = n^4*(cN+beta)
        float Ns = fmaf(sN, Ap, -cN * Bp);         // = n^4*sN
        float rinv = frsq(fmaf(Nc, Nc, Ns * Ns));
        float cT = Nc * rinv;                      // cos(Theta)
        float sT = Ns * rinv;                      // sin(Theta)

        float k2 = (1.0f - cT) * rm * rm;          // (1-cos)/m^2
        float sv = sT * rm;                        // sin/m

        float xy = qx*qy, xz = qx*qz, yz = qy*qz;
        float G[9];
        G[0] = fmaf(k2, xx, cT);
        G[1] = fmaf(k2, xy, -sv*qz);
        G[2] = fmaf(k2, xz,  sv*qy);
        G[3] = fmaf(k2, xy,  sv*qz);
        G[4] = fmaf(k2, yy, cT);
        G[5] = fmaf(k2, yz, -sv*qx);
        G[6] = fmaf(k2, xz, -sv*qy);
        G[7] = fmaf(k2, yz,  sv*qx);
        G[8] = fmaf(k2, zz, cT);
        // det(G) > 0 always => no sign term for the gt side.

        float sig = sp;

        // ---- M = P^T @ G ; rot contribution ----
        float rot = 0.0f;
        #pragma unroll
        for (int i = 0; i < 3; ++i) {
            #pragma unroll
            for (int k = 0; k < 3; ++k) {
                float mm = fmaf(P[i], G[k], fmaf(P[3+i], G[3+k], P[6+i]*G[6+k]));
                mm = sig * mm - ((i == k) ? 1.0f : 0.0f);
                rot = fmaf(mm, mm, rot);
            }
        }

        // ---- translation ----
        float t0 = pt0 - gt0;
        float t1 = pt1 - gt1;
        float t2 = pt2 - gt2;
        float tl = fmaf(t0, t0, fmaf(t1, t1, t2*t2));

        v = rot * (1.0f/9.0f) + tl * (1.0f/3.0f);
    }

    // ---- block reduction ----
    #pragma unroll
    for (int o = 16; o > 0; o >>= 1) v += __shfl_xor_sync(0xFFFFFFFFu, v, o);

    __shared__ float sh[TPB / 32];
    int lane = tid & 31;
    int warp = tid >> 5;
    if (lane == 0) sh[warp] = v;
    __syncthreads();
    if (warp == 0) {
        v = (lane < TPB/32) ? sh[lane] : 0.0f;
        #pragma unroll
        for (int o = 16; o > 0; o >>= 1) v += __shfl_xor_sync(0xFFFFFFFFu, v, o);
        if (lane == 0) {
            atomicAdd(&g_accum, (double)v);
            __threadfence();
            unsigned int prev = atomicAdd(&g_count, 1u);
            if (prev == (unsigned int)(nblocks - 1)) {
                double total = atomicAdd(&g_accum, 0.0);   // atomic read at L2
                *out = (float)(total / (double)B);
                g_accum = 0.0;                              // reset for next replay
                g_count = 0u;
            }
        }
    }
}

extern "C" void kernel_launch(void* const* d_in, const int* in_sizes, int n_in,
                              void* d_out, int out_size) {
    (void)n_in; (void)out_size;
    const float* pred_R = (const float*)d_in[0];
    const float* pred_t = (const float*)d_in[1];
    const float* gt     = (const float*)d_in[2];
    int B = in_sizes[0] / 9;

    int blocks = (B + TPB - 1) / TPB;
    se3_loss_kernel<<<blocks, TPB>>>(pred_R, pred_t, gt, (float*)d_out, B, blocks);
}

// round 16
// speedup vs baseline: 1.5936x; 1.0505x over previous
#include <cuda_runtime.h>

// ---------------------------------------------------------------------------
// SE3 loss, single fused kernel (scalar fp32):
//   rot_loss = mean( (polar_norm(pred_R)^T @ polar_norm(quat_to_R(gt_q)) - I)^2 )
//   t_loss   = mean( (pred_t - gt_t)^2 )
//
// pred_R path: polar via 3 Frobenius-scaled Newton iters + 1 Newton-Schulz.
// gt path: ANALYTIC polar of the unnormalized-quat matrix
//     G = n^2*Rhat + (1-n^2)*I  =>  polar(G) = Rot(u, Theta), det(G) > 0.
// Epilogue: TRACE IDENTITY. P, G rotations =>
//     ||sp*P^T G - I||^2 = 6 - 2*sp*tr(P^T G)
//   and with G = cT*I + sv*K(q) + k2*q q^T:
//     tr(P^T G) = cT*tr(P) + sv*<P,K(q)> + k2*(q^T P q)
//   so G is never materialized.
// Grid reduction: block shuffle-reduce -> atomicAdd(double) -> last-block
// finalize + reset of device globals (graph-replay safe).
// ---------------------------------------------------------------------------

#define TPB 256

__device__ double g_accum = 0.0;
__device__ unsigned int g_count = 0u;

__device__ __forceinline__ float frcp(float x)  { float r; asm("rcp.approx.f32 %0, %1;"   : "=f"(r) : "f"(x)); return r; }
__device__ __forceinline__ float frsq(float x)  { float r; asm("rsqrt.approx.f32 %0, %1;" : "=f"(r) : "f"(x)); return r; }
__device__ __forceinline__ float fsqr(float x)  { float r; asm("sqrt.approx.f32 %0, %1;"  : "=f"(r) : "f"(x)); return r; }

// In-place polar factor of row-major 3x3. Returns sign(det) of the original.
__device__ __forceinline__ float polar3x3(float X[9]) {
    float sgn = 1.0f;
    #pragma unroll
    for (int it = 0; it < 3; ++it) {
        // cofactor matrix, row-major (so X^{-T} = C * (1/det))
        float c0 = fmaf(X[4], X[8], -X[5]*X[7]);
        float c1 = fmaf(X[5], X[6], -X[3]*X[8]);
        float c2 = fmaf(X[3], X[7], -X[4]*X[6]);
        float c3 = fmaf(X[2], X[7], -X[1]*X[8]);
        float c4 = fmaf(X[0], X[8], -X[2]*X[6]);
        float c5 = fmaf(X[1], X[6], -X[0]*X[7]);
        float c6 = fmaf(X[1], X[5], -X[2]*X[4]);
        float c7 = fmaf(X[2], X[3], -X[0]*X[5]);
        float c8 = fmaf(X[0], X[4], -X[1]*X[3]);
        float det = fmaf(X[0], c0, fmaf(X[1], c1, X[2]*c2));
        if (it == 0) {
            sgn = __int_as_float((__float_as_int(det) & 0x80000000) | 0x3F800000);
        }
        float rdet = frcp(det);

        float nx = X[0]*X[0];
        #pragma unroll
        for (int i = 1; i < 9; ++i) nx = fmaf(X[i], X[i], nx);
        float nc = c0*c0;
        nc = fmaf(c1,c1,nc); nc = fmaf(c2,c2,nc); nc = fmaf(c3,c3,nc);
        nc = fmaf(c4,c4,nc); nc = fmaf(c5,c5,nc); nc = fmaf(c6,c6,nc);
        nc = fmaf(c7,c7,nc); nc = fmaf(c8,c8,nc);

        // mu = (nc/(nx*det^2))^{1/4}; with p = nc*rdet^2, w = rsqrt(p*nx):
        //   a = 0.5*mu = 0.5*sqrt(p*w);  b = 0.5*rdet/mu = rdet*(nx*w)*a
        float p = nc * rdet * rdet;
        float w = frsq(p * nx);
        float a = 0.5f * fsqr(p * w);
        float b = rdet * (nx * w) * a;

        X[0] = fmaf(a, X[0], b*c0);
        X[1] = fmaf(a, X[1], b*c1);
        X[2] = fmaf(a, X[2], b*c2);
        X[3] = fmaf(a, X[3], b*c3);
        X[4] = fmaf(a, X[4], b*c4);
        X[5] = fmaf(a, X[5], b*c5);
        X[6] = fmaf(a, X[6], b*c6);
        X[7] = fmaf(a, X[7], b*c7);
        X[8] = fmaf(a, X[8], b*c8);
    }

    // Final Newton-Schulz step: X <- X * (1.5I - 0.5 * X^T X)
    {
        float s00 = fmaf(X[0], X[0], fmaf(X[3], X[3], X[6]*X[6]));
        float s11 = fmaf(X[1], X[1], fmaf(X[4], X[4], X[7]*X[7]));
        float s22 = fmaf(X[2], X[2], fmaf(X[5], X[5], X[8]*X[8]));
        float s01 = fmaf(X[0], X[1], fmaf(X[3], X[4], X[6]*X[7]));
        float s02 = fmaf(X[0], X[2], fmaf(X[3], X[5], X[6]*X[8]));
        float s12 = fmaf(X[1], X[2], fmaf(X[4], X[5], X[7]*X[8]));
        float d0 = fmaf(-0.5f, s00, 1.5f);
        float d1 = fmaf(-0.5f, s11, 1.5f);
        float d2 = fmaf(-0.5f, s22, 1.5f);
        float o01 = -0.5f * s01;
        float o02 = -0.5f * s02;
        float o12 = -0.5f * s12;
        #pragma unroll
        for (int r = 0; r < 3; ++r) {
            float x0 = X[3*r+0], x1 = X[3*r+1], x2 = X[3*r+2];
            X[3*r+0] = fmaf(x0, d0,  fmaf(x1, o01, x2*o02));
            X[3*r+1] = fmaf(x0, o01, fmaf(x1, d1,  x2*o12));
            X[3*r+2] = fmaf(x0, o02, fmaf(x1, o12, x2*d2 ));
        }
    }
    return sgn;
}

__global__ void __launch_bounds__(TPB)
se3_loss_kernel(const float* __restrict__ pred_R,
                const float* __restrict__ pred_t,
                const float* __restrict__ gt,
                float* __restrict__ out,
                int B, int nblocks) {
    __shared__ float sR[TPB * 9];   // 9216 B
    __shared__ float sQ[TPB * 7];   // 7168 B

    const int tid = threadIdx.x;
    const size_t base = (size_t)blockIdx.x * TPB;
    const bool full = (base + TPB <= (size_t)B);

    // ---- coalesced float4 staging into shared (R and gt only) ----
    if (full) {
        const float4* r4 = (const float4*)(pred_R + base * 9);   // 576 float4
        float4* s4 = (float4*)sR;
        #pragma unroll
        for (int i = 0; i < 3; ++i) {
            int j = tid + i * TPB;
            if (j < (TPB*9)/4) s4[j] = r4[j];
        }
        const float4* q4 = (const float4*)(gt + base * 7);       // 448 float4
        float4* sq4 = (float4*)sQ;
        #pragma unroll
        for (int i = 0; i < 2; ++i) {
            int j = tid + i * TPB;
            if (j < (TPB*7)/4) sq4[j] = q4[j];
        }
    } else {
        int n = (int)((size_t)B > base ? (size_t)B - base : 0);
        for (int j = tid; j < n * 9; j += TPB) sR[j] = pred_R[base * 9 + j];
        for (int j = tid; j < n * 7; j += TPB) sQ[j] = gt[base * 7 + j];
    }
    __syncthreads();

    float v = 0.0f;
    const int idx = (int)base + tid;
    if (idx < B) {
        // pred_t direct (3 lines/warp per LDG, issues early, overlaps compute)
        const float* tp = pred_t + (size_t)idx * 3;
        float pt0 = __ldg(tp + 0), pt1 = __ldg(tp + 1), pt2 = __ldg(tp + 2);

        // ---- pred rotation: iterative polar ----
        float P[9];
        #pragma unroll
        for (int i = 0; i < 9; ++i) P[i] = sR[tid * 9 + i];
        float sp = polar3x3(P);

        // ---- gt: analytic polar angle of the quat matrix ----
        float qw = sQ[tid*7+0], qx = sQ[tid*7+1], qy = sQ[tid*7+2], qz = sQ[tid*7+3];
        float gt0 = sQ[tid*7+4], gt1 = sQ[tid*7+5], gt2 = sQ[tid*7+6];

        float m2 = fmaf(qx, qx, fmaf(qy, qy, qz*qz));
        float n2 = fmaf(qw, qw, m2);
        float rm = frsq(fmaxf(m2, 1e-30f));       // 1/m
        float m  = m2 * rm;                        // m = |(x,y,z)|

        float cN = fmaf(qw, qw, -m2);              // n2*cos(theta)
        float sN = 2.0f * qw * m;                  // n2*sin(theta)
        float beta = 1.0f - n2;
        float Ap = fmaf(n2, n2, beta * cN);
        float Bp = beta * sN;

        float Nc = fmaf(cN, Ap,  sN * Bp);         // = n^4*(cN+beta)
        float Ns = fmaf(sN, Ap, -cN * Bp);         // = n^4*sN
        float rinv = frsq(fmaf(Nc, Nc, Ns * Ns));
        float cT = Nc * rinv;                      // cos(Theta)
        float sT = Ns * rinv;                      // sin(Theta)

        float k2 = (1.0f - cT) * rm * rm;          // (1-cos)/m^2
        float sv = sT * rm;                        // sin/m

        // ---- TRACE IDENTITY epilogue: rot = 6 - 2*sp*tr(P^T G) ----
        // tr(P^T G) = cT*tr(P) + sv*<P,K(q)> + k2*(q^T P q)
        float trP   = P[0] + P[4] + P[8];
        float cross = fmaf(qx, P[7]-P[5], fmaf(qy, P[2]-P[6], qz*(P[3]-P[1])));
        float r0 = fmaf(P[0], qx, fmaf(P[1], qy, P[2]*qz));
        float r1 = fmaf(P[3], qx, fmaf(P[4], qy, P[5]*qz));
        float r2 = fmaf(P[6], qx, fmaf(P[7], qy, P[8]*qz));
        float quad = fmaf(qx, r0, fmaf(qy, r1, qz*r2));
        float trPG = fmaf(cT, trP, fmaf(sv, cross, k2*quad));
        float rot  = fmaf(-2.0f*sp, trPG, 6.0f);

        // ---- translation ----
        float t0 = pt0 - gt0;
        float t1 = pt1 - gt1;
        float t2 = pt2 - gt2;
        float tl = fmaf(t0, t0, fmaf(t1, t1, t2*t2));

        v = rot * (1.0f/9.0f) + tl * (1.0f/3.0f);
    }

    // ---- block reduction ----
    #pragma unroll
    for (int o = 16; o > 0; o >>= 1) v += __shfl_xor_sync(0xFFFFFFFFu, v, o);

    __shared__ float sh[TPB / 32];
    int lane = tid & 31;
    int warp = tid >> 5;
    if (lane == 0) sh[warp] = v;
    __syncthreads();
    if (warp == 0) {
        v = (lane < TPB/32) ? sh[lane] : 0.0f;
        #pragma unroll
        for (int o = 16; o > 0; o >>= 1) v += __shfl_xor_sync(0xFFFFFFFFu, v, o);
        if (lane == 0) {
            atomicAdd(&g_accum, (double)v);
            __threadfence();
            unsigned int prev = atomicAdd(&g_count, 1u);
            if (prev == (unsigned int)(nblocks - 1)) {
                double total = atomicAdd(&g_accum, 0.0);   // atomic read at L2
                *out = (float)(total / (double)B);
                g_accum = 0.0;                              // reset for next replay
                g_count = 0u;
            }
        }
    }
}

extern "C" void kernel_launch(void* const* d_in, const int* in_sizes, int n_in,
                              void* d_out, int out_size) {
    (void)n_in; (void)out_size;
    const float* pred_R = (const float*)d_in[0];
    const float* pred_t = (const float*)d_in[1];
    const float* gt     = (const float*)d_in[2];
    int B = in_sizes[0] / 9;

    int blocks = (B + TPB - 1) / TPB;
    se3_loss_kernel<<<blocks, TPB>>>(pred_R, pred_t, gt, (float*)d_out, B, blocks);
}